// round 12
// baseline (speedup 1.0000x reference)
#include <cuda_runtime.h>
#include <cuda_bf16.h>
#include <cstdint>
#include <math.h>

#define N_  4
#define P_  2048
#define D_  512
#define H_  8
#define HD_ 64
#define QT  64
#define KTILE 32
#define NT  (P_/KTILE)   // 64
#define PT1 128          // phase-1 tile
#define NT1 (P_/PT1)     // 16
#define OUT_ELEMS   (N_*P_*D_)            // 4194304
#define ATTN_ELEMS  ((size_t)N_*H_*P_*P_) // 134217728

// ---------------- scratch -------------------------------------------------
__device__ __align__(16) __nv_bfloat16 g_q_hi[N_*H_*P_*HD_];
__device__ __align__(16) __nv_bfloat16 g_q_lo[N_*H_*P_*HD_];
__device__ __align__(16) __nv_bfloat16 g_k_hi[N_*H_*P_*HD_];
__device__ __align__(16) __nv_bfloat16 g_k_lo[N_*H_*P_*HD_];
__device__ __align__(16) __nv_bfloat16 g_v_hi[N_*H_*P_*HD_];
__device__ __align__(16) __nv_bfloat16 g_v_lo[N_*H_*P_*HD_];
__device__ __align__(16) __nv_bfloat16 g_o_hi[N_*P_*D_];
__device__ __align__(16) __nv_bfloat16 g_o_lo[N_*P_*D_];
__device__ __align__(16) __nv_bfloat16 g_wo_hi[D_*D_];
__device__ __align__(16) __nv_bfloat16 g_wo_lo[D_*D_];

// ---------------- helpers -------------------------------------------------
__device__ __forceinline__ uint32_t smem_to_u32(const void* p) {
    uint32_t a;
    asm("{ .reg .u64 t; cvta.to.shared.u64 t, %1; cvt.u32.u64 %0, t; }"
        : "=r"(a) : "l"(p));
    return a;
}
#define SWZ(b) ((b) ^ (((b) >> 3) & 0x70))

__device__ __forceinline__ void ldsm_x4(uint32_t* r, uint32_t a) {
    asm volatile("ldmatrix.sync.aligned.m8n8.x4.shared.b16 {%0,%1,%2,%3}, [%4];"
        : "=r"(r[0]), "=r"(r[1]), "=r"(r[2]), "=r"(r[3]) : "r"(a));
}
__device__ __forceinline__ void ldsm_x4_t(uint32_t* r, uint32_t a) {
    asm volatile("ldmatrix.sync.aligned.m8n8.x4.trans.shared.b16 {%0,%1,%2,%3}, [%4];"
        : "=r"(r[0]), "=r"(r[1]), "=r"(r[2]), "=r"(r[3]) : "r"(a));
}
__device__ __forceinline__ void mma_bf16(float* d, const uint32_t* a,
                                         uint32_t b0, uint32_t b1) {
    asm volatile("mma.sync.aligned.m16n8k16.row.col.f32.bf16.bf16.f32 "
        "{%0,%1,%2,%3}, {%4,%5,%6,%7}, {%8,%9}, {%0,%1,%2,%3};"
        : "+f"(d[0]), "+f"(d[1]), "+f"(d[2]), "+f"(d[3])
        : "r"(a[0]), "r"(a[1]), "r"(a[2]), "r"(a[3]), "r"(b0), "r"(b1));
}
__device__ __forceinline__ float ex2(float x) {
    float y;
    asm("ex2.approx.ftz.f32 %0, %1;" : "=f"(y) : "f"(x));
    return y;
}
__device__ __forceinline__ uint32_t pack2h(__nv_bfloat16 a, __nv_bfloat16 b) {
    __nv_bfloat162 v = __halves2bfloat162(a, b);
    return *reinterpret_cast<uint32_t*>(&v);
}
__device__ __forceinline__ uint32_t pack2f(float a, float b) {
    __nv_bfloat162 v = __floats2bfloat162_rn(a, b);
    return *reinterpret_cast<uint32_t*>(&v);
}
__device__ __forceinline__ void cp16(uint32_t dst, const void* src) {
    asm volatile("cp.async.cg.shared.global [%0], [%1], 16;"
        :: "r"(dst), "l"(src) : "memory");
}
#define CP_COMMIT() asm volatile("cp.async.commit_group;" ::: "memory")
#define CP_WAIT(n)  asm volatile("cp.async.wait_group %0;" :: "n"(n) : "memory")

// ======================= 1) QKV projection (float4 LDS, d-outer) ===========
#define QKV_RPB 8
#define WPAD 68
#define QKV_WS  (64*WPAD)
#define QKV_SMEM_FLOATS (3*QKV_WS + QKV_RPB*512)

__global__ __launch_bounds__(512) void qkv_kernel(
    const float* __restrict__ x, const float* __restrict__ Wq,
    const float* __restrict__ Wk, const float* __restrict__ Wv)
{
    extern __shared__ float sm[];
    float* ws = sm;                       // [3][64*WPAD]
    float* xs = sm + 3*QKV_WS;            // [8][512]
    int t = threadIdx.x;
    for (int i = t; i < 64*64; i += 512) {
        int e = i >> 6, d = i & 63;
        ws[0*QKV_WS + e*WPAD + d] = Wq[i];
        ws[1*QKV_WS + e*WPAD + d] = Wk[i];
        ws[2*QKV_WS + e*WPAD + d] = Wv[i];
    }
    int p0 = blockIdx.x * QKV_RPB;
    #pragma unroll
    for (int r = 0; r < QKV_RPB; r++)
        xs[r*512 + t] = x[(size_t)(p0 + r)*D_ + t];
    __syncthreads();

    const int h = t >> 6, e = t & 63;
    const float4* wq = (const float4*)(ws + 0*QKV_WS + e*WPAD);
    const float4* wk = (const float4*)(ws + 1*QKV_WS + e*WPAD);
    const float4* wv = (const float4*)(ws + 2*QKV_WS + e*WPAD);
    // (1/sqrt(512)) * log2(e): softmax computed with ex2
    const float qscale = 0.06375870113f;
    const int n = p0 >> 11, pl0 = p0 & (P_-1);
    const int nh = n*H_ + h;

    float aq[8], ak[8], av[8];
    #pragma unroll
    for (int r = 0; r < 8; r++) { aq[r] = 0.f; ak[r] = 0.f; av[r] = 0.f; }

    #pragma unroll
    for (int d4 = 0; d4 < 16; d4++) {
        float4 q4 = wq[d4], k4 = wk[d4], v4 = wv[d4];
        #pragma unroll
        for (int r = 0; r < 8; r++) {
            float4 x4 = *(const float4*)(xs + r*512 + h*HD_ + d4*4);
            aq[r] = fmaf(x4.x, q4.x, fmaf(x4.y, q4.y,
                    fmaf(x4.z, q4.z, fmaf(x4.w, q4.w, aq[r]))));
            ak[r] = fmaf(x4.x, k4.x, fmaf(x4.y, k4.y,
                    fmaf(x4.z, k4.z, fmaf(x4.w, k4.w, ak[r]))));
            av[r] = fmaf(x4.x, v4.x, fmaf(x4.y, v4.y,
                    fmaf(x4.z, v4.z, fmaf(x4.w, v4.w, av[r]))));
        }
    }

    #pragma unroll
    for (int r = 0; r < 8; r++) {
        size_t idx = ((size_t)nh*P_ + pl0 + r)*HD_ + e;
        float aqs = aq[r] * qscale;
        __nv_bfloat16 qh = __float2bfloat16(aqs);
        g_q_hi[idx] = qh;
        g_q_lo[idx] = __float2bfloat16(aqs - __bfloat162float(qh));
        __nv_bfloat16 kh = __float2bfloat16(ak[r]);
        g_k_hi[idx] = kh;
        g_k_lo[idx] = __float2bfloat16(ak[r] - __bfloat162float(kh));
        __nv_bfloat16 vh = __float2bfloat16(av[r]);
        g_v_hi[idx] = vh;
        g_v_lo[idx] = __float2bfloat16(av[r] - __bfloat162float(vh));
    }
}

// ---- Wo hi/lo split (once) ----
__global__ __launch_bounds__(256) void wsplit_kernel(const float* __restrict__ Wo)
{
    int i = blockIdx.x * 256 + threadIdx.x;
    float w = Wo[i];
    __nv_bfloat16 hh = __float2bfloat16(w);
    g_wo_hi[i] = hh;
    g_wo_lo[i] = __float2bfloat16(w - __bfloat162float(hh));
}

// ======================= 2) mma.sync attention =============================
// Phase 1: l = sum exp2(s2) via hi-chain QK^T. Phase 2: 3-chain S,
// normalized P written once, AV. 2-stage distance-1 cp.async pipeline.
#define STAGE_BYTES 16384
#define ATTN_SMEM_BYTES (1024 + 16384 + 2*STAGE_BYTES)   // 50176

__device__ __forceinline__ void prefetch_kv(
    uint32_t kvb, const uint4* ksh, const uint4* ksl,
    const uint4* vsh, const uint4* vsl, int t)
{
    #pragma unroll
    for (int u = 0; u < 2; u++) {
        int i = t + u*128;                // 32 rows x 8 uint4
        uint32_t off = SWZ((uint32_t)((i >> 3)*128 + (i & 7)*16));
        cp16(kvb + off,          ksh + i);
        cp16(kvb + 4096 + off,   ksl + i);
        cp16(kvb + 8192 + off,   vsh + i);
        cp16(kvb + 12288 + off,  vsl + i);
    }
}
__device__ __forceinline__ void prefetch_khi(uint32_t dst, const uint4* src, int t)
{
    #pragma unroll
    for (int u = 0; u < 8; u++) {
        int i = t + u*128;                // 128 rows x 8 uint4 = 16KB
        uint32_t off = SWZ((uint32_t)((i >> 3)*128 + (i & 7)*16));
        cp16(dst + off, src + i);
    }
}

__global__ __launch_bounds__(128, 4) void attn_mma_kernel(
    float* __restrict__ attn, int store_attn)
{
    extern __shared__ unsigned char smd[];
    const uint32_t sb = (smem_to_u32(smd) + 1023u) & ~1023u;
    unsigned char* smb = smd + (sb - smem_to_u32(smd));
    const int t = threadIdx.x, w = t >> 5, lane = t & 31;
    const int g = lane >> 2, q = lane & 3;
    const int qt = blockIdx.x, h = blockIdx.y, n = blockIdx.z, nh = n*H_ + h;

    const uint32_t SQH = 0, SQL = 8192, KV0 = 16384;

    // ---- stage Q (64x64 bf16 hi/lo), swizzled ----
    const uint4* qh_g = (const uint4*)(g_q_hi + ((size_t)nh*P_ + qt*QT)*HD_);
    const uint4* ql_g = (const uint4*)(g_q_lo + ((size_t)nh*P_ + qt*QT)*HD_);
    for (int i = t; i < 512; i += 128) {
        uint32_t off = SWZ((uint32_t)((i >> 3)*128 + (i & 7)*16));
        *(uint4*)(smb + SQH + off) = qh_g[i];
        *(uint4*)(smb + SQL + off) = ql_g[i];
    }

    const uint4* kh_g = (const uint4*)(g_k_hi + (size_t)nh*P_*HD_);
    const uint4* kl_g = (const uint4*)(g_k_lo + (size_t)nh*P_*HD_);
    const uint4* vh_g = (const uint4*)(g_v_hi + (size_t)nh*P_*HD_);
    const uint4* vl_g = (const uint4*)(g_v_lo + (size_t)nh*P_*HD_);

    // ================= PHASE 1: l precompute (K_hi only) =================
    prefetch_khi(sb + KV0, kh_g, t);
    CP_COMMIT();
    __syncthreads();   // Q staged (plain STS) before ldsm

    uint32_t qa_h[4][4], qa_l[4][4];
    {
        uint32_t row = (uint32_t)(w*16 + (lane & 15));
        #pragma unroll
        for (int ks = 0; ks < 4; ks++) {
            uint32_t off = SWZ(row*128 + (uint32_t)(2*ks + (lane >> 4))*16);
            ldsm_x4(qa_h[ks], sb + SQH + off);
            ldsm_x4(qa_l[ks], sb + SQL + off);
        }
    }

    float ls0 = 0.f, ls1 = 0.f;
    for (int pt = 0; pt < NT1; pt++) {
        if (pt + 1 < NT1) {
            prefetch_khi(sb + KV0 + (uint32_t)((pt + 1) & 1)*STAGE_BYTES,
                         kh_g + (pt+1)*1024, t);
            CP_COMMIT();
            CP_WAIT(1);
        } else {
            CP_WAIT(0);
        }
        __syncthreads();
        const uint32_t SKH = sb + KV0 + (uint32_t)(pt & 1)*STAGE_BYTES;
        #pragma unroll
        for (int nb = 0; nb < 16; nb++) {
            float sa[4] = {0.f, 0.f, 0.f, 0.f};
            uint32_t kb[2][4];
            #pragma unroll
            for (int a2 = 0; a2 < 2; a2++) {
                uint32_t off = SWZ((uint32_t)(8*nb + (lane & 7))*128
                                 + (uint32_t)(4*a2 + (lane >> 3))*16);
                ldsm_x4(kb[a2], SKH + off);
            }
            #pragma unroll
            for (int ks = 0; ks < 4; ks++) {
                int a2 = ks >> 1, mo = (ks & 1)*2;
                mma_bf16(sa, qa_h[ks], kb[a2][mo], kb[a2][mo+1]);
            }
            ls0 += ex2(sa[0]) + ex2(sa[1]);
            ls1 += ex2(sa[2]) + ex2(sa[3]);
        }
        __syncthreads();
    }
    ls0 += __shfl_xor_sync(0xffffffffu, ls0, 1);
    ls0 += __shfl_xor_sync(0xffffffffu, ls0, 2);
    ls1 += __shfl_xor_sync(0xffffffffu, ls1, 1);
    ls1 += __shfl_xor_sync(0xffffffffu, ls1, 2);
    const float inv0 = 1.f / ls0, inv1 = 1.f / ls1;

    // ================= PHASE 2: full S, normalized P, AV =================
    prefetch_kv(sb + KV0, kh_g, kl_g, vh_g, vl_g, t);
    CP_COMMIT();

    float o_acc[8][4];
    #pragma unroll
    for (int i = 0; i < 8; i++)
        #pragma unroll
        for (int j = 0; j < 4; j++) o_acc[i][j] = 0.f;

    float* arow0 = attn + ((size_t)nh*P_ + (size_t)(qt*QT + w*16 + g))*P_;
    float* arow1 = arow0 + 8*(size_t)P_;

    for (int kt = 0; kt < NT; kt++) {
        if (kt + 1 < NT) {
            prefetch_kv(sb + KV0 + (uint32_t)((kt + 1) & 1)*STAGE_BYTES,
                        kh_g + (kt+1)*256, kl_g + (kt+1)*256,
                        vh_g + (kt+1)*256, vl_g + (kt+1)*256, t);
            CP_COMMIT();
            CP_WAIT(1);
        } else {
            CP_WAIT(0);
        }
        __syncthreads();
        const uint32_t kvb = sb + KV0 + (uint32_t)(kt & 1)*STAGE_BYTES;
        const uint32_t SKH = kvb, SKL = kvb + 4096,
                       SVH = kvb + 8192, SVL = kvb + 12288;

        uint32_t pa_h[2][4], pa_l[2][4];
        #pragma unroll
        for (int nb = 0; nb < 4; nb++) {
            float sa[4] = {0.f, 0.f, 0.f, 0.f};
            uint32_t kb_h[2][4], kb_l[2][4];
            #pragma unroll
            for (int a2 = 0; a2 < 2; a2++) {
                uint32_t off = SWZ((uint32_t)(8*nb + (lane & 7))*128
                                 + (uint32_t)(4*a2 + (lane >> 3))*16);
                ldsm_x4(kb_h[a2], SKH + off);
                ldsm_x4(kb_l[a2], SKL + off);
            }
            #pragma unroll
            for (int ks = 0; ks < 4; ks++) {
                int a2 = ks >> 1, mo = (ks & 1)*2;
                mma_bf16(sa, qa_h[ks], kb_h[a2][mo], kb_h[a2][mo+1]);
                mma_bf16(sa, qa_h[ks], kb_l[a2][mo], kb_l[a2][mo+1]);
                mma_bf16(sa, qa_l[ks], kb_h[a2][mo], kb_h[a2][mo+1]);
            }
            float p0 = ex2(sa[0]) * inv0, p1 = ex2(sa[1]) * inv0;
            float p2 = ex2(sa[2]) * inv1, p3 = ex2(sa[3]) * inv1;
            if (store_attn) {
                *(float2*)(arow0 + (size_t)kt*KTILE + 8*nb + 2*q) = make_float2(p0, p1);
                *(float2*)(arow1 + (size_t)kt*KTILE + 8*nb + 2*q) = make_float2(p2, p3);
            }
            __nv_bfloat16 h0 = __float2bfloat16(p0), h1 = __float2bfloat16(p1);
            __nv_bfloat16 h2 = __float2bfloat16(p2), h3 = __float2bfloat16(p3);
            int ks2 = nb >> 1, sl = (nb & 1)*2;
            pa_h[ks2][sl]   = pack2h(h0, h1);
            pa_h[ks2][sl+1] = pack2h(h2, h3);
            pa_l[ks2][sl]   = pack2f(p0 - __bfloat162float(h0), p1 - __bfloat162float(h1));
            pa_l[ks2][sl+1] = pack2f(p2 - __bfloat162float(h2), p3 - __bfloat162float(h3));
        }

        #pragma unroll
        for (int nb2 = 0; nb2 < 8; nb2++) {
            uint32_t vb_h[4], vb_l[4];
            uint32_t off = SWZ((uint32_t)lane*128 + (uint32_t)nb2*16);
            ldsm_x4_t(vb_h, SVH + off);
            ldsm_x4_t(vb_l, SVL + off);
            #pragma unroll
            for (int ks2 = 0; ks2 < 2; ks2++) {
                int mo = ks2*2;
                mma_bf16(o_acc[nb2], pa_h[ks2], vb_h[mo], vb_h[mo+1]);
                mma_bf16(o_acc[nb2], pa_h[ks2], vb_l[mo], vb_l[mo+1]);
                mma_bf16(o_acc[nb2], pa_l[ks2], vb_h[mo], vb_h[mo+1]);
            }
        }
        __syncthreads();
    }

    // ---- epilogue: O already normalized; write bf16 hi/lo ----
    int r0 = qt*QT + w*16 + g;
    size_t ob0 = ((size_t)n*P_ + r0)*D_ + h*HD_;
    size_t ob1 = ob0 + 8*(size_t)D_;
    #pragma unroll
    for (int nb2 = 0; nb2 < 8; nb2++) {
        float v0 = o_acc[nb2][0], v1 = o_acc[nb2][1];
        float v2 = o_acc[nb2][2], v3 = o_acc[nb2][3];
        __nv_bfloat16 h0 = __float2bfloat16(v0), h1 = __float2bfloat16(v1);
        __nv_bfloat16 h2 = __float2bfloat16(v2), h3 = __float2bfloat16(v3);
        int c = 8*nb2 + 2*q;
        *(uint32_t*)&g_o_hi[ob0 + c] = pack2h(h0, h1);
        *(uint32_t*)&g_o_lo[ob0 + c] = pack2f(v0 - __bfloat162float(h0),
                                              v1 - __bfloat162float(h1));
        *(uint32_t*)&g_o_hi[ob1 + c] = pack2h(h2, h3);
        *(uint32_t*)&g_o_lo[ob1 + c] = pack2f(v2 - __bfloat162float(h2),
                                              v3 - __bfloat162float(h3));
    }
}

// ======================= 3) output projection (pipelined mma) ==============
#define PROJ_STAGE 32768
#define PROJ_SMEM_BYTES (1024 + 2*PROJ_STAGE)   // 66560

__device__ __forceinline__ void proj_prefetch(uint32_t st, int rb, int cb,
                                              int ktile, int t)
{
    #pragma unroll
    for (int u = 0; u < 4; u++) {
        int i = t + u*128;
        int row = i >> 3, c8 = i & 7;
        uint32_t off = SWZ((uint32_t)(row*128 + c8*16));
        cp16(st + off,
             g_o_hi + (size_t)(rb + row)*D_ + ktile*64 + c8*8);
        cp16(st + 8192 + off,
             g_o_lo + (size_t)(rb + row)*D_ + ktile*64 + c8*8);
        cp16(st + 16384 + off,
             g_wo_hi + (size_t)(cb + row)*D_ + ktile*64 + c8*8);
        cp16(st + 24576 + off,
             g_wo_lo + (size_t)(cb + row)*D_ + ktile*64 + c8*8);
    }
}

__global__ __launch_bounds__(128) void proj_mma_kernel(
    const float* __restrict__ bo, float* __restrict__ out)
{
    extern __shared__ unsigned char smd[];
    const uint32_t sb = (smem_to_u32(smd) + 1023u) & ~1023u;
    const int t = threadIdx.x, w = t >> 5, lane = t & 31;
    const int g = lane >> 2, q = lane & 3;
    const int rb = blockIdx.x * 64, cb = blockIdx.y * 64;

    float acc[8][4];
    #pragma unroll
    for (int i = 0; i < 8; i++)
        #pragma unroll
        for (int j = 0; j < 4; j++) acc[i][j] = 0.f;

    proj_prefetch(sb, rb, cb, 0, t);
    CP_COMMIT();

    for (int ktile = 0; ktile < 8; ktile++) {
        if (ktile + 1 < 8) {
            proj_prefetch(sb + (uint32_t)((ktile + 1) & 1)*PROJ_STAGE,
                          rb, cb, ktile + 1, t);
            CP_COMMIT();
            CP_WAIT(1);
        } else {
            CP_WAIT(0);
        }
        __syncthreads();
        const uint32_t st = sb + (uint32_t)(ktile & 1)*PROJ_STAGE;
        const uint32_t AH = st, AL = st + 8192, BH = st + 16384, BL = st + 24576;

        uint32_t ah[4][4], al[4][4];
        {
            uint32_t row = (uint32_t)(w*16 + (lane & 15));
            #pragma unroll
            for (int ks = 0; ks < 4; ks++) {
                uint32_t off = SWZ(row*128 + (uint32_t)(2*ks + (lane >> 4))*16);
                ldsm_x4(ah[ks], AH + off);
                ldsm_x4(al[ks], AL + off);
            }
        }
        #pragma unroll
        for (int nb = 0; nb < 8; nb++) {
            uint32_t bh[2][4], bl[2][4];
            #pragma unroll
            for (int a2 = 0; a2 < 2; a2++) {
                uint32_t off = SWZ((uint32_t)(8*nb + (lane & 7))*128
                                 + (uint32_t)(4*a2 + (lane >> 3))*16);
                ldsm_x4(bh[a2], BH + off);
                ldsm_x4(bl[a2], BL + off);
            }
            #pragma unroll
            for (int ks = 0; ks < 4; ks++) {
                int a2 = ks >> 1, mo = (ks & 1)*2;
                mma_bf16(acc[nb], ah[ks], bh[a2][mo], bh[a2][mo+1]);
                mma_bf16(acc[nb], ah[ks], bl[a2][mo], bl[a2][mo+1]);
                mma_bf16(acc[nb], al[ks], bh[a2][mo], bh[a2][mo+1]);
            }
        }
        __syncthreads();
    }

    int r0 = rb + w*16 + g;
    #pragma unroll
    for (int nb = 0; nb < 8; nb++) {
        int c = cb + 8*nb + 2*q;
        float b0 = bo[c], b1 = bo[c + 1];
        *(float2*)(out + (size_t)r0*D_ + c) =
            make_float2(acc[nb][0] + b0, acc[nb][1] + b1);
        *(float2*)(out + (size_t)(r0 + 8)*D_ + c) =
            make_float2(acc[nb][2] + b0, acc[nb][3] + b1);
    }
}

// ======================= launch ============================================
extern "C" void kernel_launch(void* const* d_in, const int* in_sizes, int n_in,
                              void* d_out, int out_size)
{
    const float* xyz = (const float*)d_in[0];
    const float* Wq  = (const float*)d_in[1];
    const float* Wk  = (const float*)d_in[2];
    const float* Wv  = (const float*)d_in[3];
    const float* Wo  = (const float*)d_in[4];
    const float* bo  = (const float*)d_in[5];
    float* out = (float*)d_out;

    int store_attn = (out_size >= (int)(OUT_ELEMS + ATTN_ELEMS)) ? 1 : 0;
    float* attn = store_attn ? (out + OUT_ELEMS) : out;

    cudaFuncSetAttribute(qkv_kernel, cudaFuncAttributeMaxDynamicSharedMemorySize,
                         QKV_SMEM_FLOATS * 4);
    cudaFuncSetAttribute(attn_mma_kernel, cudaFuncAttributeMaxDynamicSharedMemorySize,
                         ATTN_SMEM_BYTES);
    cudaFuncSetAttribute(proj_mma_kernel, cudaFuncAttributeMaxDynamicSharedMemorySize,
                         PROJ_SMEM_BYTES);

    qkv_kernel<<<(N_*P_)/QKV_RPB, 512, QKV_SMEM_FLOATS*4>>>(xyz, Wq, Wk, Wv);
    wsplit_kernel<<<(D_*D_)/256, 256>>>(Wo);
    attn_mma_kernel<<<dim3(P_/QT, H_, N_), 128, ATTN_SMEM_BYTES>>>(attn, store_attn);
    proj_mma_kernel<<<dim3((N_*P_)/64, D_/64), 128, PROJ_SMEM_BYTES>>>(bo, out);
}

// round 13
// speedup vs baseline: 1.4290x; 1.4290x over previous
#include <cuda_runtime.h>
#include <cuda_bf16.h>
#include <cstdint>
#include <math.h>

#define N_  4
#define P_  2048
#define D_  512
#define H_  8
#define HD_ 64
#define QT  64
#define KTILE 32
#define NT  (P_/KTILE)   // 64
#define PT1 128          // phase-1 tile
#define NT1 (P_/PT1)     // 16
#define OUT_ELEMS   (N_*P_*D_)            // 4194304
#define ATTN_ELEMS  ((size_t)N_*H_*P_*P_) // 134217728

// ---------------- scratch -------------------------------------------------
__device__ __align__(16) __nv_bfloat16 g_q_hi[N_*H_*P_*HD_];
__device__ __align__(16) __nv_bfloat16 g_q_lo[N_*H_*P_*HD_];
__device__ __align__(16) __nv_bfloat16 g_k_hi[N_*H_*P_*HD_];
__device__ __align__(16) __nv_bfloat16 g_k_lo[N_*H_*P_*HD_];
__device__ __align__(16) __nv_bfloat16 g_v_hi[N_*H_*P_*HD_];
__device__ __align__(16) __nv_bfloat16 g_v_lo[N_*H_*P_*HD_];
__device__ __align__(16) __nv_bfloat16 g_o_hi[N_*P_*D_];
__device__ __align__(16) __nv_bfloat16 g_o_lo[N_*P_*D_];
__device__ __align__(16) __nv_bfloat16 g_wo_hi[D_*D_];
__device__ __align__(16) __nv_bfloat16 g_wo_lo[D_*D_];

// ---------------- helpers -------------------------------------------------
__device__ __forceinline__ uint32_t smem_to_u32(const void* p) {
    uint32_t a;
    asm("{ .reg .u64 t; cvta.to.shared.u64 t, %1; cvt.u32.u64 %0, t; }"
        : "=r"(a) : "l"(p));
    return a;
}
#define SWZ(b) ((b) ^ (((b) >> 3) & 0x70))

__device__ __forceinline__ void ldsm_x4(uint32_t* r, uint32_t a) {
    asm volatile("ldmatrix.sync.aligned.m8n8.x4.shared.b16 {%0,%1,%2,%3}, [%4];"
        : "=r"(r[0]), "=r"(r[1]), "=r"(r[2]), "=r"(r[3]) : "r"(a));
}
__device__ __forceinline__ void ldsm_x4_t(uint32_t* r, uint32_t a) {
    asm volatile("ldmatrix.sync.aligned.m8n8.x4.trans.shared.b16 {%0,%1,%2,%3}, [%4];"
        : "=r"(r[0]), "=r"(r[1]), "=r"(r[2]), "=r"(r[3]) : "r"(a));
}
__device__ __forceinline__ void mma_bf16(float* d, const uint32_t* a,
                                         uint32_t b0, uint32_t b1) {
    asm volatile("mma.sync.aligned.m16n8k16.row.col.f32.bf16.bf16.f32 "
        "{%0,%1,%2,%3}, {%4,%5,%6,%7}, {%8,%9}, {%0,%1,%2,%3};"
        : "+f"(d[0]), "+f"(d[1]), "+f"(d[2]), "+f"(d[3])
        : "r"(a[0]), "r"(a[1]), "r"(a[2]), "r"(a[3]), "r"(b0), "r"(b1));
}
__device__ __forceinline__ float ex2(float x) {
    float y;
    asm("ex2.approx.ftz.f32 %0, %1;" : "=f"(y) : "f"(x));
    return y;
}
__device__ __forceinline__ uint32_t pack2h(__nv_bfloat16 a, __nv_bfloat16 b) {
    __nv_bfloat162 v = __halves2bfloat162(a, b);
    return *reinterpret_cast<uint32_t*>(&v);
}
__device__ __forceinline__ uint32_t pack2f(float a, float b) {
    __nv_bfloat162 v = __floats2bfloat162_rn(a, b);
    return *reinterpret_cast<uint32_t*>(&v);
}
__device__ __forceinline__ void cp16(uint32_t dst, const void* src) {
    asm volatile("cp.async.cg.shared.global [%0], [%1], 16;"
        :: "r"(dst), "l"(src) : "memory");
}
#define CP_COMMIT() asm volatile("cp.async.commit_group;" ::: "memory")
#define CP_WAIT(n)  asm volatile("cp.async.wait_group %0;" :: "n"(n) : "memory")

// ======================= 1) QKV projection (float4 LDS, d-outer) ===========
#define QKV_RPB 8
#define WPAD 68
#define QKV_WS  (64*WPAD)
#define QKV_SMEM_FLOATS (3*QKV_WS + QKV_RPB*512)

__global__ __launch_bounds__(512) void qkv_kernel(
    const float* __restrict__ x, const float* __restrict__ Wq,
    const float* __restrict__ Wk, const float* __restrict__ Wv)
{
    extern __shared__ float sm[];
    float* ws = sm;                       // [3][64*WPAD]
    float* xs = sm + 3*QKV_WS;            // [8][512]
    int t = threadIdx.x;
    for (int i = t; i < 64*64; i += 512) {
        int e = i >> 6, d = i & 63;
        ws[0*QKV_WS + e*WPAD + d] = Wq[i];
        ws[1*QKV_WS + e*WPAD + d] = Wk[i];
        ws[2*QKV_WS + e*WPAD + d] = Wv[i];
    }
    int p0 = blockIdx.x * QKV_RPB;
    #pragma unroll
    for (int r = 0; r < QKV_RPB; r++)
        xs[r*512 + t] = x[(size_t)(p0 + r)*D_ + t];
    __syncthreads();

    const int h = t >> 6, e = t & 63;
    const float4* wq = (const float4*)(ws + 0*QKV_WS + e*WPAD);
    const float4* wk = (const float4*)(ws + 1*QKV_WS + e*WPAD);
    const float4* wv = (const float4*)(ws + 2*QKV_WS + e*WPAD);
    // (1/sqrt(512)) * log2(e): softmax computed with ex2
    const float qscale = 0.06375870113f;
    const int n = p0 >> 11, pl0 = p0 & (P_-1);
    const int nh = n*H_ + h;

    float aq[8], ak[8], av[8];
    #pragma unroll
    for (int r = 0; r < 8; r++) { aq[r] = 0.f; ak[r] = 0.f; av[r] = 0.f; }

    #pragma unroll
    for (int d4 = 0; d4 < 16; d4++) {
        float4 q4 = wq[d4], k4 = wk[d4], v4 = wv[d4];
        #pragma unroll
        for (int r = 0; r < 8; r++) {
            float4 x4 = *(const float4*)(xs + r*512 + h*HD_ + d4*4);
            aq[r] = fmaf(x4.x, q4.x, fmaf(x4.y, q4.y,
                    fmaf(x4.z, q4.z, fmaf(x4.w, q4.w, aq[r]))));
            ak[r] = fmaf(x4.x, k4.x, fmaf(x4.y, k4.y,
                    fmaf(x4.z, k4.z, fmaf(x4.w, k4.w, ak[r]))));
            av[r] = fmaf(x4.x, v4.x, fmaf(x4.y, v4.y,
                    fmaf(x4.z, v4.z, fmaf(x4.w, v4.w, av[r]))));
        }
    }

    #pragma unroll
    for (int r = 0; r < 8; r++) {
        size_t idx = ((size_t)nh*P_ + pl0 + r)*HD_ + e;
        float aqs = aq[r] * qscale;
        __nv_bfloat16 qh = __float2bfloat16(aqs);
        g_q_hi[idx] = qh;
        g_q_lo[idx] = __float2bfloat16(aqs - __bfloat162float(qh));
        __nv_bfloat16 kh = __float2bfloat16(ak[r]);
        g_k_hi[idx] = kh;
        g_k_lo[idx] = __float2bfloat16(ak[r] - __bfloat162float(kh));
        __nv_bfloat16 vh = __float2bfloat16(av[r]);
        g_v_hi[idx] = vh;
        g_v_lo[idx] = __float2bfloat16(av[r] - __bfloat162float(vh));
    }
}

// ---- Wo hi/lo split (once) ----
__global__ __launch_bounds__(256) void wsplit_kernel(const float* __restrict__ Wo)
{
    int i = blockIdx.x * 256 + threadIdx.x;
    float w = Wo[i];
    __nv_bfloat16 hh = __float2bfloat16(w);
    g_wo_hi[i] = hh;
    g_wo_lo[i] = __float2bfloat16(w - __bfloat162float(hh));
}

// ======================= 2) mma.sync attention =============================
// Phase 1: l = sum exp2(s2) via hi-chain QK^T (PT1=128 tiles, K_hi only).
// Phase 2: full 3-chain S, write normalized P once, AV accumulate.
// 3-stage distance-2 cp.async pipeline; occupancy 3 (no reg cap below natural).
#define STAGE_BYTES 16384
#define ATTN_SMEM_BYTES (1024 + 16384 + 3*STAGE_BYTES)

__device__ __forceinline__ void prefetch_kv(
    uint32_t kvb, const uint4* ksh, const uint4* ksl,
    const uint4* vsh, const uint4* vsl, int t)
{
    #pragma unroll
    for (int u = 0; u < 2; u++) {
        int i = t + u*128;                // 32 rows x 8 uint4
        uint32_t off = SWZ((uint32_t)((i >> 3)*128 + (i & 7)*16));
        cp16(kvb + off,          ksh + i);
        cp16(kvb + 4096 + off,   ksl + i);
        cp16(kvb + 8192 + off,   vsh + i);
        cp16(kvb + 12288 + off,  vsl + i);
    }
}
__device__ __forceinline__ void prefetch_khi(uint32_t dst, const uint4* src, int t)
{
    #pragma unroll
    for (int u = 0; u < 8; u++) {
        int i = t + u*128;                // 128 rows x 8 uint4 = 16KB
        uint32_t off = SWZ((uint32_t)((i >> 3)*128 + (i & 7)*16));
        cp16(dst + off, src + i);
    }
}

__global__ __launch_bounds__(128, 3) void attn_mma_kernel(
    float* __restrict__ attn, int store_attn)
{
    extern __shared__ unsigned char smd[];
    const uint32_t sb = (smem_to_u32(smd) + 1023u) & ~1023u;
    unsigned char* smb = smd + (sb - smem_to_u32(smd));
    const int t = threadIdx.x, w = t >> 5, lane = t & 31;
    const int g = lane >> 2, q = lane & 3;
    const int qt = blockIdx.x, h = blockIdx.y, n = blockIdx.z, nh = n*H_ + h;

    const uint32_t SQH = 0, SQL = 8192, KV0 = 16384;

    // ---- stage Q (64x64 bf16 hi/lo), swizzled ----
    const uint4* qh_g = (const uint4*)(g_q_hi + ((size_t)nh*P_ + qt*QT)*HD_);
    const uint4* ql_g = (const uint4*)(g_q_lo + ((size_t)nh*P_ + qt*QT)*HD_);
    for (int i = t; i < 512; i += 128) {
        uint32_t off = SWZ((uint32_t)((i >> 3)*128 + (i & 7)*16));
        *(uint4*)(smb + SQH + off) = qh_g[i];
        *(uint4*)(smb + SQL + off) = ql_g[i];
    }

    const uint4* kh_g = (const uint4*)(g_k_hi + (size_t)nh*P_*HD_);
    const uint4* kl_g = (const uint4*)(g_k_lo + (size_t)nh*P_*HD_);
    const uint4* vh_g = (const uint4*)(g_v_hi + (size_t)nh*P_*HD_);
    const uint4* vl_g = (const uint4*)(g_v_lo + (size_t)nh*P_*HD_);

    // ================= PHASE 1: l precompute (K_hi only) =================
    prefetch_khi(sb + KV0, kh_g, t);
    CP_COMMIT();
    prefetch_khi(sb + KV0 + STAGE_BYTES, kh_g + 1024, t);
    CP_COMMIT();
    __syncthreads();

    // Q a-frags (hi/lo; lo used in phase 2)
    uint32_t qa_h[4][4], qa_l[4][4];
    {
        uint32_t row = (uint32_t)(w*16 + (lane & 15));
        #pragma unroll
        for (int ks = 0; ks < 4; ks++) {
            uint32_t off = SWZ(row*128 + (uint32_t)(2*ks + (lane >> 4))*16);
            ldsm_x4(qa_h[ks], sb + SQH + off);
            ldsm_x4(qa_l[ks], sb + SQL + off);
        }
    }

    float ls0 = 0.f, ls1 = 0.f;
    int stage = 0;
    for (int pt = 0; pt < NT1; pt++) {
        if (pt + 2 < NT1) {
            int ws_ = stage + 2; if (ws_ >= 3) ws_ -= 3;
            prefetch_khi(sb + KV0 + (uint32_t)ws_*STAGE_BYTES,
                         kh_g + (pt+2)*1024, t);
            CP_COMMIT();
            CP_WAIT(2);
        } else if (pt + 1 < NT1) {
            CP_WAIT(1);
        } else {
            CP_WAIT(0);
        }
        __syncthreads();
        const uint32_t SKH = sb + KV0 + (uint32_t)stage*STAGE_BYTES;
        #pragma unroll
        for (int nb = 0; nb < 16; nb++) {
            float sa[4] = {0.f, 0.f, 0.f, 0.f};
            uint32_t kb[2][4];
            #pragma unroll
            for (int a2 = 0; a2 < 2; a2++) {
                uint32_t off = SWZ((uint32_t)(8*nb + (lane & 7))*128
                                 + (uint32_t)(4*a2 + (lane >> 3))*16);
                ldsm_x4(kb[a2], SKH + off);
            }
            #pragma unroll
            for (int ks = 0; ks < 4; ks++) {
                int a2 = ks >> 1, mo = (ks & 1)*2;
                mma_bf16(sa, qa_h[ks], kb[a2][mo], kb[a2][mo+1]);
            }
            ls0 += ex2(sa[0]) + ex2(sa[1]);
            ls1 += ex2(sa[2]) + ex2(sa[3]);
        }
        __syncthreads();
        if (++stage == 3) stage = 0;
    }
    // reduce l across quad, broadcast inverse
    ls0 += __shfl_xor_sync(0xffffffffu, ls0, 1);
    ls0 += __shfl_xor_sync(0xffffffffu, ls0, 2);
    ls1 += __shfl_xor_sync(0xffffffffu, ls1, 1);
    ls1 += __shfl_xor_sync(0xffffffffu, ls1, 2);
    const float inv0 = 1.f / ls0, inv1 = 1.f / ls1;

    // ================= PHASE 2: full S, normalized P, AV =================
    prefetch_kv(sb + KV0, kh_g, kl_g, vh_g, vl_g, t);
    CP_COMMIT();
    prefetch_kv(sb + KV0 + STAGE_BYTES, kh_g + 256, kl_g + 256,
                vh_g + 256, vl_g + 256, t);
    CP_COMMIT();

    float o_acc[8][4];
    #pragma unroll
    for (int i = 0; i < 8; i++)
        #pragma unroll
        for (int j = 0; j < 4; j++) o_acc[i][j] = 0.f;

    float* arow0 = attn + ((size_t)nh*P_ + (size_t)(qt*QT + w*16 + g))*P_;
    float* arow1 = arow0 + 8*(size_t)P_;

    stage = 0;
    for (int kt = 0; kt < NT; kt++) {
        if (kt + 2 < NT) {
            int ws_ = stage + 2; if (ws_ >= 3) ws_ -= 3;
            prefetch_kv(sb + KV0 + (uint32_t)ws_*STAGE_BYTES,
                        kh_g + (kt+2)*256, kl_g + (kt+2)*256,
                        vh_g + (kt+2)*256, vl_g + (kt+2)*256, t);
            CP_COMMIT();
            CP_WAIT(2);
        } else if (kt + 1 < NT) {
            CP_WAIT(1);
        } else {
            CP_WAIT(0);
        }
        __syncthreads();
        const uint32_t kvb = sb + KV0 + (uint32_t)stage*STAGE_BYTES;
        const uint32_t SKH = kvb, SKL = kvb + 4096,
                       SVH = kvb + 8192, SVL = kvb + 12288;

        uint32_t pa_h[2][4], pa_l[2][4];
        #pragma unroll
        for (int nb = 0; nb < 4; nb++) {
            float sa[4] = {0.f, 0.f, 0.f, 0.f};
            uint32_t kb_h[2][4], kb_l[2][4];
            #pragma unroll
            for (int a2 = 0; a2 < 2; a2++) {
                uint32_t off = SWZ((uint32_t)(8*nb + (lane & 7))*128
                                 + (uint32_t)(4*a2 + (lane >> 3))*16);
                ldsm_x4(kb_h[a2], SKH + off);
                ldsm_x4(kb_l[a2], SKL + off);
            }
            #pragma unroll
            for (int ks = 0; ks < 4; ks++) {
                int a2 = ks >> 1, mo = (ks & 1)*2;
                mma_bf16(sa, qa_h[ks], kb_h[a2][mo], kb_h[a2][mo+1]);
                mma_bf16(sa, qa_h[ks], kb_l[a2][mo], kb_l[a2][mo+1]);
                mma_bf16(sa, qa_l[ks], kb_h[a2][mo], kb_h[a2][mo+1]);
            }
            float p0 = ex2(sa[0]) * inv0, p1 = ex2(sa[1]) * inv0;
            float p2 = ex2(sa[2]) * inv1, p3 = ex2(sa[3]) * inv1;
            if (store_attn) {
                *(float2*)(arow0 + (size_t)kt*KTILE + 8*nb + 2*q) = make_float2(p0, p1);
                *(float2*)(arow1 + (size_t)kt*KTILE + 8*nb + 2*q) = make_float2(p2, p3);
            }
            __nv_bfloat16 h0 = __float2bfloat16(p0), h1 = __float2bfloat16(p1);
            __nv_bfloat16 h2 = __float2bfloat16(p2), h3 = __float2bfloat16(p3);
            int ks2 = nb >> 1, sl = (nb & 1)*2;
            pa_h[ks2][sl]   = pack2h(h0, h1);
            pa_h[ks2][sl+1] = pack2h(h2, h3);
            pa_l[ks2][sl]   = pack2f(p0 - __bfloat162float(h0), p1 - __bfloat162float(h1));
            pa_l[ks2][sl+1] = pack2f(p2 - __bfloat162float(h2), p3 - __bfloat162float(h3));
        }

        // O += P V (normalized P)
        #pragma unroll
        for (int nb2 = 0; nb2 < 8; nb2++) {
            uint32_t vb_h[4], vb_l[4];
            uint32_t off = SWZ((uint32_t)lane*128 + (uint32_t)nb2*16);
            ldsm_x4_t(vb_h, SVH + off);
            ldsm_x4_t(vb_l, SVL + off);
            #pragma unroll
            for (int ks2 = 0; ks2 < 2; ks2++) {
                int mo = ks2*2;
                mma_bf16(o_acc[nb2], pa_h[ks2], vb_h[mo], vb_h[mo+1]);
                mma_bf16(o_acc[nb2], pa_h[ks2], vb_l[mo], vb_l[mo+1]);
                mma_bf16(o_acc[nb2], pa_l[ks2], vb_h[mo], vb_h[mo+1]);
            }
        }
        __syncthreads();
        if (++stage == 3) stage = 0;
    }

    // ---- epilogue: O already normalized; write bf16 hi/lo ----
    int r0 = qt*QT + w*16 + g;
    size_t ob0 = ((size_t)n*P_ + r0)*D_ + h*HD_;
    size_t ob1 = ob0 + 8*(size_t)D_;
    #pragma unroll
    for (int nb2 = 0; nb2 < 8; nb2++) {
        float v0 = o_acc[nb2][0], v1 = o_acc[nb2][1];
        float v2 = o_acc[nb2][2], v3 = o_acc[nb2][3];
        __nv_bfloat16 h0 = __float2bfloat16(v0), h1 = __float2bfloat16(v1);
        __nv_bfloat16 h2 = __float2bfloat16(v2), h3 = __float2bfloat16(v3);
        int c = 8*nb2 + 2*q;
        *(uint32_t*)&g_o_hi[ob0 + c] = pack2h(h0, h1);
        *(uint32_t*)&g_o_lo[ob0 + c] = pack2f(v0 - __bfloat162float(h0),
                                              v1 - __bfloat162float(h1));
        *(uint32_t*)&g_o_hi[ob1 + c] = pack2h(h2, h3);
        *(uint32_t*)&g_o_lo[ob1 + c] = pack2f(v2 - __bfloat162float(h2),
                                              v3 - __bfloat162float(h3));
    }
}

// ======================= 3) output projection (pipelined mma) ==============
#define PROJ_STAGE 32768
#define PROJ_SMEM_BYTES (1024 + 2*PROJ_STAGE)   // 66560

__device__ __forceinline__ void proj_prefetch(uint32_t st, int rb, int cb,
                                              int ktile, int t)
{
    #pragma unroll
    for (int u = 0; u < 4; u++) {
        int i = t + u*128;
        int row = i >> 3, c8 = i & 7;
        uint32_t off = SWZ((uint32_t)(row*128 + c8*16));
        cp16(st + off,
             g_o_hi + (size_t)(rb + row)*D_ + ktile*64 + c8*8);
        cp16(st + 8192 + off,
             g_o_lo + (size_t)(rb + row)*D_ + ktile*64 + c8*8);
        cp16(st + 16384 + off,
             g_wo_hi + (size_t)(cb + row)*D_ + ktile*64 + c8*8);
        cp16(st + 24576 + off,
             g_wo_lo + (size_t)(cb + row)*D_ + ktile*64 + c8*8);
    }
}

__global__ __launch_bounds__(128) void proj_mma_kernel(
    const float* __restrict__ bo, float* __restrict__ out)
{
    extern __shared__ unsigned char smd[];
    const uint32_t sb = (smem_to_u32(smd) + 1023u) & ~1023u;
    const int t = threadIdx.x, w = t >> 5, lane = t & 31;
    const int g = lane >> 2, q = lane & 3;
    const int rb = blockIdx.x * 64, cb = blockIdx.y * 64;

    float acc[8][4];
    #pragma unroll
    for (int i = 0; i < 8; i++)
        #pragma unroll
        for (int j = 0; j < 4; j++) acc[i][j] = 0.f;

    proj_prefetch(sb, rb, cb, 0, t);
    CP_COMMIT();

    for (int ktile = 0; ktile < 8; ktile++) {
        if (ktile + 1 < 8) {
            proj_prefetch(sb + (uint32_t)((ktile + 1) & 1)*PROJ_STAGE,
                          rb, cb, ktile + 1, t);
            CP_COMMIT();
            CP_WAIT(1);
        } else {
            CP_WAIT(0);
        }
        __syncthreads();
        const uint32_t st = sb + (uint32_t)(ktile & 1)*PROJ_STAGE;
        const uint32_t AH = st, AL = st + 8192, BH = st + 16384, BL = st + 24576;

        uint32_t ah[4][4], al[4][4];
        {
            uint32_t row = (uint32_t)(w*16 + (lane & 15));
            #pragma unroll
            for (int ks = 0; ks < 4; ks++) {
                uint32_t off = SWZ(row*128 + (uint32_t)(2*ks + (lane >> 4))*16);
                ldsm_x4(ah[ks], AH + off);
                ldsm_x4(al[ks], AL + off);
            }
        }
        #pragma unroll
        for (int nb = 0; nb < 8; nb++) {
            uint32_t bh[2][4], bl[2][4];
            #pragma unroll
            for (int a2 = 0; a2 < 2; a2++) {
                uint32_t off = SWZ((uint32_t)(8*nb + (lane & 7))*128
                                 + (uint32_t)(4*a2 + (lane >> 3))*16);
                ldsm_x4(bh[a2], BH + off);
                ldsm_x4(bl[a2], BL + off);
            }
            #pragma unroll
            for (int ks = 0; ks < 4; ks++) {
                int a2 = ks >> 1, mo = (ks & 1)*2;
                mma_bf16(acc[nb], ah[ks], bh[a2][mo], bh[a2][mo+1]);
                mma_bf16(acc[nb], ah[ks], bl[a2][mo], bl[a2][mo+1]);
                mma_bf16(acc[nb], al[ks], bh[a2][mo], bh[a2][mo+1]);
            }
        }
        __syncthreads();
    }

    int r0 = rb + w*16 + g;
    #pragma unroll
    for (int nb = 0; nb < 8; nb++) {
        int c = cb + 8*nb + 2*q;
        float b0 = bo[c], b1 = bo[c + 1];
        *(float2*)(out + (size_t)r0*D_ + c) =
            make_float2(acc[nb][0] + b0, acc[nb][1] + b1);
        *(float2*)(out + (size_t)(r0 + 8)*D_ + c) =
            make_float2(acc[nb][2] + b0, acc[nb][3] + b1);
    }
}

// ======================= launch ============================================
extern "C" void kernel_launch(void* const* d_in, const int* in_sizes, int n_in,
                              void* d_out, int out_size)
{
    const float* xyz = (const float*)d_in[0];
    const float* Wq  = (const float*)d_in[1];
    const float* Wk  = (const float*)d_in[2];
    const float* Wv  = (const float*)d_in[3];
    const float* Wo  = (const float*)d_in[4];
    const float* bo  = (const float*)d_in[5];
    float* out = (float*)d_out;

    int store_attn = (out_size >= (int)(OUT_ELEMS + ATTN_ELEMS)) ? 1 : 0;
    float* attn = store_attn ? (out + OUT_ELEMS) : out;

    cudaFuncSetAttribute(qkv_kernel, cudaFuncAttributeMaxDynamicSharedMemorySize,
                         QKV_SMEM_FLOATS * 4);
    cudaFuncSetAttribute(attn_mma_kernel, cudaFuncAttributeMaxDynamicSharedMemorySize,
                         ATTN_SMEM_BYTES);
    cudaFuncSetAttribute(proj_mma_kernel, cudaFuncAttributeMaxDynamicSharedMemorySize,
                         PROJ_SMEM_BYTES);

    qkv_kernel<<<(N_*P_)/QKV_RPB, 512, QKV_SMEM_FLOATS*4>>>(xyz, Wq, Wk, Wv);
    wsplit_kernel<<<(D_*D_)/256, 256>>>(Wo);
    attn_mma_kernel<<<dim3(P_/QT, H_, N_), 128, ATTN_SMEM_BYTES>>>(attn, store_attn);
    proj_mma_kernel<<<dim3((N_*P_)/64, D_/64), 128, PROJ_SMEM_BYTES>>>(bo, out);
}

// round 14
// speedup vs baseline: 1.5015x; 1.0507x over previous
#include <cuda_runtime.h>
#include <cuda_bf16.h>
#include <cstdint>
#include <math.h>

#define N_  4
#define P_  2048
#define D_  512
#define H_  8
#define HD_ 64
#define QT  64
#define KTILE 32
#define NT  (P_/KTILE)   // 64
#define PT1 128          // phase-1 tile
#define NT1 (P_/PT1)     // 16
#define OUT_ELEMS   (N_*P_*D_)            // 4194304
#define ATTN_ELEMS  ((size_t)N_*H_*P_*P_) // 134217728

// ---------------- scratch -------------------------------------------------
__device__ __align__(16) __nv_bfloat16 g_q_hi[N_*H_*P_*HD_];
__device__ __align__(16) __nv_bfloat16 g_q_lo[N_*H_*P_*HD_];
__device__ __align__(16) __nv_bfloat16 g_k_hi[N_*H_*P_*HD_];
__device__ __align__(16) __nv_bfloat16 g_v_hi[N_*H_*P_*HD_];
__device__ __align__(16) __nv_bfloat16 g_v_lo[N_*H_*P_*HD_];
__device__ __align__(16) __nv_bfloat16 g_o_hi[N_*P_*D_];
__device__ __align__(16) __nv_bfloat16 g_o_lo[N_*P_*D_];
__device__ __align__(16) __nv_bfloat16 g_wo_hi[D_*D_];
__device__ __align__(16) __nv_bfloat16 g_wo_lo[D_*D_];

// ---------------- helpers -------------------------------------------------
__device__ __forceinline__ uint32_t smem_to_u32(const void* p) {
    uint32_t a;
    asm("{ .reg .u64 t; cvta.to.shared.u64 t, %1; cvt.u32.u64 %0, t; }"
        : "=r"(a) : "l"(p));
    return a;
}
#define SWZ(b) ((b) ^ (((b) >> 3) & 0x70))

__device__ __forceinline__ void ldsm_x4(uint32_t* r, uint32_t a) {
    asm volatile("ldmatrix.sync.aligned.m8n8.x4.shared.b16 {%0,%1,%2,%3}, [%4];"
        : "=r"(r[0]), "=r"(r[1]), "=r"(r[2]), "=r"(r[3]) : "r"(a));
}
__device__ __forceinline__ void ldsm_x4_t(uint32_t* r, uint32_t a) {
    asm volatile("ldmatrix.sync.aligned.m8n8.x4.trans.shared.b16 {%0,%1,%2,%3}, [%4];"
        : "=r"(r[0]), "=r"(r[1]), "=r"(r[2]), "=r"(r[3]) : "r"(a));
}
__device__ __forceinline__ void mma_bf16(float* d, const uint32_t* a,
                                         uint32_t b0, uint32_t b1) {
    asm volatile("mma.sync.aligned.m16n8k16.row.col.f32.bf16.bf16.f32 "
        "{%0,%1,%2,%3}, {%4,%5,%6,%7}, {%8,%9}, {%0,%1,%2,%3};"
        : "+f"(d[0]), "+f"(d[1]), "+f"(d[2]), "+f"(d[3])
        : "r"(a[0]), "r"(a[1]), "r"(a[2]), "r"(a[3]), "r"(b0), "r"(b1));
}
__device__ __forceinline__ float ex2(float x) {
    float y;
    asm("ex2.approx.ftz.f32 %0, %1;" : "=f"(y) : "f"(x));
    return y;
}
__device__ __forceinline__ uint32_t pack2h(__nv_bfloat16 a, __nv_bfloat16 b) {
    __nv_bfloat162 v = __halves2bfloat162(a, b);
    return *reinterpret_cast<uint32_t*>(&v);
}
__device__ __forceinline__ uint32_t pack2f(float a, float b) {
    __nv_bfloat162 v = __floats2bfloat162_rn(a, b);
    return *reinterpret_cast<uint32_t*>(&v);
}
__device__ __forceinline__ void cp16(uint32_t dst, const void* src) {
    asm volatile("cp.async.cg.shared.global [%0], [%1], 16;"
        :: "r"(dst), "l"(src) : "memory");
}
#define CP_COMMIT() asm volatile("cp.async.commit_group;" ::: "memory")
#define CP_WAIT(n)  asm volatile("cp.async.wait_group %0;" :: "n"(n) : "memory")

// ======================= 1) QKV projection + Wo split ======================
#define QKV_RPB 8
#define WPAD 68
#define QKV_WS  (64*WPAD)
#define QKV_SMEM_FLOATS (3*QKV_WS + QKV_RPB*512)

__global__ __launch_bounds__(512) void qkv_kernel(
    const float* __restrict__ x, const float* __restrict__ Wq,
    const float* __restrict__ Wk, const float* __restrict__ Wv,
    const float* __restrict__ Wo)
{
    extern __shared__ float sm[];
    float* ws = sm;                       // [3][64*WPAD]
    float* xs = sm + 3*QKV_WS;            // [8][512]
    int t = threadIdx.x;

    // fused Wo hi/lo split: 262144 elems over 1024 blocks x 256 lanes
    if (t < 256) {
        int i = blockIdx.x * 256 + t;
        float wv_ = Wo[i];
        __nv_bfloat16 hh = __float2bfloat16(wv_);
        g_wo_hi[i] = hh;
        g_wo_lo[i] = __float2bfloat16(wv_ - __bfloat162float(hh));
    }

    for (int i = t; i < 64*64; i += 512) {
        int e = i >> 6, d = i & 63;
        ws[0*QKV_WS + e*WPAD + d] = Wq[i];
        ws[1*QKV_WS + e*WPAD + d] = Wk[i];
        ws[2*QKV_WS + e*WPAD + d] = Wv[i];
    }
    int p0 = blockIdx.x * QKV_RPB;
    #pragma unroll
    for (int r = 0; r < QKV_RPB; r++)
        xs[r*512 + t] = x[(size_t)(p0 + r)*D_ + t];
    __syncthreads();

    const int h = t >> 6, e = t & 63;
    const float4* wq = (const float4*)(ws + 0*QKV_WS + e*WPAD);
    const float4* wk = (const float4*)(ws + 1*QKV_WS + e*WPAD);
    const float4* wv = (const float4*)(ws + 2*QKV_WS + e*WPAD);
    // (1/sqrt(512)) * log2(e): softmax computed with ex2
    const float qscale = 0.06375870113f;
    const int n = p0 >> 11, pl0 = p0 & (P_-1);
    const int nh = n*H_ + h;

    float aq[8], ak[8], av[8];
    #pragma unroll
    for (int r = 0; r < 8; r++) { aq[r] = 0.f; ak[r] = 0.f; av[r] = 0.f; }

    #pragma unroll
    for (int d4 = 0; d4 < 16; d4++) {
        float4 q4 = wq[d4], k4 = wk[d4], v4 = wv[d4];
        #pragma unroll
        for (int r = 0; r < 8; r++) {
            float4 x4 = *(const float4*)(xs + r*512 + h*HD_ + d4*4);
            aq[r] = fmaf(x4.x, q4.x, fmaf(x4.y, q4.y,
                    fmaf(x4.z, q4.z, fmaf(x4.w, q4.w, aq[r]))));
            ak[r] = fmaf(x4.x, k4.x, fmaf(x4.y, k4.y,
                    fmaf(x4.z, k4.z, fmaf(x4.w, k4.w, ak[r]))));
            av[r] = fmaf(x4.x, v4.x, fmaf(x4.y, v4.y,
                    fmaf(x4.z, v4.z, fmaf(x4.w, v4.w, av[r]))));
        }
    }

    #pragma unroll
    for (int r = 0; r < 8; r++) {
        size_t idx = ((size_t)nh*P_ + pl0 + r)*HD_ + e;
        float aqs = aq[r] * qscale;
        __nv_bfloat16 qh = __float2bfloat16(aqs);
        g_q_hi[idx] = qh;
        g_q_lo[idx] = __float2bfloat16(aqs - __bfloat162float(qh));
        g_k_hi[idx] = __float2bfloat16(ak[r]);
        __nv_bfloat16 vh = __float2bfloat16(av[r]);
        g_v_hi[idx] = vh;
        g_v_lo[idx] = __float2bfloat16(av[r] - __bfloat162float(vh));
    }
}

// ======================= 2) mma.sync attention =============================
// Phase 1: l = sum exp2(s) via QhKh only (PT1=128 tiles).
// Phase 2: S = QhKh + QlKh (K_lo not used at all), normalized P written once,
// AV 3-chain. 3-stage distance-2 cp.async pipeline, occupancy 3, natural regs.
#define STAGE_BYTES 16384
#define ATTN_SMEM_BYTES (1024 + 16384 + 3*STAGE_BYTES)

// phase-2 stage layout: KH 4KB @0, VH 4KB @4096, VL 4KB @8192 (12KB used)
__device__ __forceinline__ void prefetch_kv(
    uint32_t kvb, const uint4* ksh,
    const uint4* vsh, const uint4* vsl, int t)
{
    #pragma unroll
    for (int u = 0; u < 2; u++) {
        int i = t + u*128;                // 32 rows x 8 uint4
        uint32_t off = SWZ((uint32_t)((i >> 3)*128 + (i & 7)*16));
        cp16(kvb + off,          ksh + i);
        cp16(kvb + 4096 + off,   vsh + i);
        cp16(kvb + 8192 + off,   vsl + i);
    }
}
__device__ __forceinline__ void prefetch_khi(uint32_t dst, const uint4* src, int t)
{
    #pragma unroll
    for (int u = 0; u < 8; u++) {
        int i = t + u*128;                // 128 rows x 8 uint4 = 16KB
        uint32_t off = SWZ((uint32_t)((i >> 3)*128 + (i & 7)*16));
        cp16(dst + off, src + i);
    }
}

__global__ __launch_bounds__(128, 3) void attn_mma_kernel(
    float* __restrict__ attn, int store_attn)
{
    extern __shared__ unsigned char smd[];
    const uint32_t sb = (smem_to_u32(smd) + 1023u) & ~1023u;
    unsigned char* smb = smd + (sb - smem_to_u32(smd));
    const int t = threadIdx.x, w = t >> 5, lane = t & 31;
    const int g = lane >> 2, q = lane & 3;
    const int qt = blockIdx.x, h = blockIdx.y, n = blockIdx.z, nh = n*H_ + h;

    const uint32_t SQH = 0, SQL = 8192, KV0 = 16384;

    // ---- stage Q (64x64 bf16 hi/lo), swizzled ----
    const uint4* qh_g = (const uint4*)(g_q_hi + ((size_t)nh*P_ + qt*QT)*HD_);
    const uint4* ql_g = (const uint4*)(g_q_lo + ((size_t)nh*P_ + qt*QT)*HD_);
    for (int i = t; i < 512; i += 128) {
        uint32_t off = SWZ((uint32_t)((i >> 3)*128 + (i & 7)*16));
        *(uint4*)(smb + SQH + off) = qh_g[i];
        *(uint4*)(smb + SQL + off) = ql_g[i];
    }

    const uint4* kh_g = (const uint4*)(g_k_hi + (size_t)nh*P_*HD_);
    const uint4* vh_g = (const uint4*)(g_v_hi + (size_t)nh*P_*HD_);
    const uint4* vl_g = (const uint4*)(g_v_lo + (size_t)nh*P_*HD_);

    // ================= PHASE 1: l precompute (K_hi only) =================
    prefetch_khi(sb + KV0, kh_g, t);
    CP_COMMIT();
    prefetch_khi(sb + KV0 + STAGE_BYTES, kh_g + 1024, t);
    CP_COMMIT();
    __syncthreads();

    uint32_t qa_h[4][4], qa_l[4][4];
    {
        uint32_t row = (uint32_t)(w*16 + (lane & 15));
        #pragma unroll
        for (int ks = 0; ks < 4; ks++) {
            uint32_t off = SWZ(row*128 + (uint32_t)(2*ks + (lane >> 4))*16);
            ldsm_x4(qa_h[ks], sb + SQH + off);
            ldsm_x4(qa_l[ks], sb + SQL + off);
        }
    }

    float ls0 = 0.f, ls1 = 0.f;
    int stage = 0;
    for (int pt = 0; pt < NT1; pt++) {
        if (pt + 2 < NT1) {
            int ws_ = stage + 2; if (ws_ >= 3) ws_ -= 3;
            prefetch_khi(sb + KV0 + (uint32_t)ws_*STAGE_BYTES,
                         kh_g + (pt+2)*1024, t);
            CP_COMMIT();
            CP_WAIT(2);
        } else if (pt + 1 < NT1) {
            CP_WAIT(1);
        } else {
            CP_WAIT(0);
        }
        __syncthreads();
        const uint32_t SKH = sb + KV0 + (uint32_t)stage*STAGE_BYTES;
        #pragma unroll
        for (int nb = 0; nb < 16; nb++) {
            float sa[4] = {0.f, 0.f, 0.f, 0.f};
            uint32_t kb[2][4];
            #pragma unroll
            for (int a2 = 0; a2 < 2; a2++) {
                uint32_t off = SWZ((uint32_t)(8*nb + (lane & 7))*128
                                 + (uint32_t)(4*a2 + (lane >> 3))*16);
                ldsm_x4(kb[a2], SKH + off);
            }
            #pragma unroll
            for (int ks = 0; ks < 4; ks++) {
                int a2 = ks >> 1, mo = (ks & 1)*2;
                mma_bf16(sa, qa_h[ks], kb[a2][mo], kb[a2][mo+1]);
            }
            ls0 += ex2(sa[0]) + ex2(sa[1]);
            ls1 += ex2(sa[2]) + ex2(sa[3]);
        }
        __syncthreads();
        if (++stage == 3) stage = 0;
    }
    ls0 += __shfl_xor_sync(0xffffffffu, ls0, 1);
    ls0 += __shfl_xor_sync(0xffffffffu, ls0, 2);
    ls1 += __shfl_xor_sync(0xffffffffu, ls1, 1);
    ls1 += __shfl_xor_sync(0xffffffffu, ls1, 2);
    const float inv0 = 1.f / ls0, inv1 = 1.f / ls1;

    // ================= PHASE 2: S (2-chain), normalized P, AV ============
    prefetch_kv(sb + KV0, kh_g, vh_g, vl_g, t);
    CP_COMMIT();
    prefetch_kv(sb + KV0 + STAGE_BYTES, kh_g + 256, vh_g + 256, vl_g + 256, t);
    CP_COMMIT();

    float o_acc[8][4];
    #pragma unroll
    for (int i = 0; i < 8; i++)
        #pragma unroll
        for (int j = 0; j < 4; j++) o_acc[i][j] = 0.f;

    float* arow0 = attn + ((size_t)nh*P_ + (size_t)(qt*QT + w*16 + g))*P_;
    float* arow1 = arow0 + 8*(size_t)P_;

    stage = 0;
    for (int kt = 0; kt < NT; kt++) {
        if (kt + 2 < NT) {
            int ws_ = stage + 2; if (ws_ >= 3) ws_ -= 3;
            prefetch_kv(sb + KV0 + (uint32_t)ws_*STAGE_BYTES,
                        kh_g + (kt+2)*256, vh_g + (kt+2)*256,
                        vl_g + (kt+2)*256, t);
            CP_COMMIT();
            CP_WAIT(2);
        } else if (kt + 1 < NT) {
            CP_WAIT(1);
        } else {
            CP_WAIT(0);
        }
        __syncthreads();
        const uint32_t kvb = sb + KV0 + (uint32_t)stage*STAGE_BYTES;
        const uint32_t SKH = kvb, SVH = kvb + 4096, SVL = kvb + 8192;

        uint32_t pa_h[2][4], pa_l[2][4];
        #pragma unroll
        for (int nb = 0; nb < 4; nb++) {
            float sa[4] = {0.f, 0.f, 0.f, 0.f};
            uint32_t kb_h[2][4];
            #pragma unroll
            for (int a2 = 0; a2 < 2; a2++) {
                uint32_t off = SWZ((uint32_t)(8*nb + (lane & 7))*128
                                 + (uint32_t)(4*a2 + (lane >> 3))*16);
                ldsm_x4(kb_h[a2], SKH + off);
            }
            #pragma unroll
            for (int ks = 0; ks < 4; ks++) {
                int a2 = ks >> 1, mo = (ks & 1)*2;
                mma_bf16(sa, qa_h[ks], kb_h[a2][mo], kb_h[a2][mo+1]);
                mma_bf16(sa, qa_l[ks], kb_h[a2][mo], kb_h[a2][mo+1]);
            }
            float p0 = ex2(sa[0]) * inv0, p1 = ex2(sa[1]) * inv0;
            float p2 = ex2(sa[2]) * inv1, p3 = ex2(sa[3]) * inv1;
            if (store_attn) {
                *(float2*)(arow0 + (size_t)kt*KTILE + 8*nb + 2*q) = make_float2(p0, p1);
                *(float2*)(arow1 + (size_t)kt*KTILE + 8*nb + 2*q) = make_float2(p2, p3);
            }
            __nv_bfloat16 h0 = __float2bfloat16(p0), h1 = __float2bfloat16(p1);
            __nv_bfloat16 h2 = __float2bfloat16(p2), h3 = __float2bfloat16(p3);
            int ks2 = nb >> 1, sl = (nb & 1)*2;
            pa_h[ks2][sl]   = pack2h(h0, h1);
            pa_h[ks2][sl+1] = pack2h(h2, h3);
            pa_l[ks2][sl]   = pack2f(p0 - __bfloat162float(h0), p1 - __bfloat162float(h1));
            pa_l[ks2][sl+1] = pack2f(p2 - __bfloat162float(h2), p3 - __bfloat162float(h3));
        }

        // O += P V (normalized P), 3 chains
        #pragma unroll
        for (int nb2 = 0; nb2 < 8; nb2++) {
            uint32_t vb_h[4], vb_l[4];
            uint32_t off = SWZ((uint32_t)lane*128 + (uint32_t)nb2*16);
            ldsm_x4_t(vb_h, SVH + off);
            ldsm_x4_t(vb_l, SVL + off);
            #pragma unroll
            for (int ks2 = 0; ks2 < 2; ks2++) {
                int mo = ks2*2;
                mma_bf16(o_acc[nb2], pa_h[ks2], vb_h[mo], vb_h[mo+1]);
                mma_bf16(o_acc[nb2], pa_h[ks2], vb_l[mo], vb_l[mo+1]);
                mma_bf16(o_acc[nb2], pa_l[ks2], vb_h[mo], vb_h[mo+1]);
            }
        }
        __syncthreads();
        if (++stage == 3) stage = 0;
    }

    // ---- epilogue: O already normalized; write bf16 hi/lo ----
    int r0 = qt*QT + w*16 + g;
    size_t ob0 = ((size_t)n*P_ + r0)*D_ + h*HD_;
    size_t ob1 = ob0 + 8*(size_t)D_;
    #pragma unroll
    for (int nb2 = 0; nb2 < 8; nb2++) {
        float v0 = o_acc[nb2][0], v1 = o_acc[nb2][1];
        float v2 = o_acc[nb2][2], v3 = o_acc[nb2][3];
        __nv_bfloat16 h0 = __float2bfloat16(v0), h1 = __float2bfloat16(v1);
        __nv_bfloat16 h2 = __float2bfloat16(v2), h3 = __float2bfloat16(v3);
        int c = 8*nb2 + 2*q;
        *(uint32_t*)&g_o_hi[ob0 + c] = pack2h(h0, h1);
        *(uint32_t*)&g_o_lo[ob0 + c] = pack2f(v0 - __bfloat162float(h0),
                                              v1 - __bfloat162float(h1));
        *(uint32_t*)&g_o_hi[ob1 + c] = pack2h(h2, h3);
        *(uint32_t*)&g_o_lo[ob1 + c] = pack2f(v2 - __bfloat162float(h2),
                                              v3 - __bfloat162float(h3));
    }
}

// ======================= 3) output projection (pipelined mma) ==============
#define PROJ_STAGE 32768
#define PROJ_SMEM_BYTES (1024 + 2*PROJ_STAGE)   // 66560

__device__ __forceinline__ void proj_prefetch(uint32_t st, int rb, int cb,
                                              int ktile, int t)
{
    #pragma unroll
    for (int u = 0; u < 4; u++) {
        int i = t + u*128;
        int row = i >> 3, c8 = i & 7;
        uint32_t off = SWZ((uint32_t)(row*128 + c8*16));
        cp16(st + off,
             g_o_hi + (size_t)(rb + row)*D_ + ktile*64 + c8*8);
        cp16(st + 8192 + off,
             g_o_lo + (size_t)(rb + row)*D_ + ktile*64 + c8*8);
        cp16(st + 16384 + off,
             g_wo_hi + (size_t)(cb + row)*D_ + ktile*64 + c8*8);
        cp16(st + 24576 + off,
             g_wo_lo + (size_t)(cb + row)*D_ + ktile*64 + c8*8);
    }
}

__global__ __launch_bounds__(128) void proj_mma_kernel(
    const float* __restrict__ bo, float* __restrict__ out)
{
    extern __shared__ unsigned char smd[];
    const uint32_t sb = (smem_to_u32(smd) + 1023u) & ~1023u;
    const int t = threadIdx.x, w = t >> 5, lane = t & 31;
    const int g = lane >> 2, q = lane & 3;
    const int rb = blockIdx.x * 64, cb = blockIdx.y * 64;

    float acc[8][4];
    #pragma unroll
    for (int i = 0; i < 8; i++)
        #pragma unroll
        for (int j = 0; j < 4; j++) acc[i][j] = 0.f;

    proj_prefetch(sb, rb, cb, 0, t);
    CP_COMMIT();

    for (int ktile = 0; ktile < 8; ktile++) {
        if (ktile + 1 < 8) {
            proj_prefetch(sb + (uint32_t)((ktile + 1) & 1)*PROJ_STAGE,
                          rb, cb, ktile + 1, t);
            CP_COMMIT();
            CP_WAIT(1);
        } else {
            CP_WAIT(0);
        }
        __syncthreads();
        const uint32_t st = sb + (uint32_t)(ktile & 1)*PROJ_STAGE;
        const uint32_t AH = st, AL = st + 8192, BH = st + 16384, BL = st + 24576;

        uint32_t ah[4][4], al[4][4];
        {
            uint32_t row = (uint32_t)(w*16 + (lane & 15));
            #pragma unroll
            for (int ks = 0; ks < 4; ks++) {
                uint32_t off = SWZ(row*128 + (uint32_t)(2*ks + (lane >> 4))*16);
                ldsm_x4(ah[ks], AH + off);
                ldsm_x4(al[ks], AL + off);
            }
        }
        #pragma unroll
        for (int nb = 0; nb < 8; nb++) {
            uint32_t bh[2][4], bl[2][4];
            #pragma unroll
            for (int a2 = 0; a2 < 2; a2++) {
                uint32_t off = SWZ((uint32_t)(8*nb + (lane & 7))*128
                                 + (uint32_t)(4*a2 + (lane >> 3))*16);
                ldsm_x4(bh[a2], BH + off);
                ldsm_x4(bl[a2], BL + off);
            }
            #pragma unroll
            for (int ks = 0; ks < 4; ks++) {
                int a2 = ks >> 1, mo = (ks & 1)*2;
                mma_bf16(acc[nb], ah[ks], bh[a2][mo], bh[a2][mo+1]);
                mma_bf16(acc[nb], ah[ks], bl[a2][mo], bl[a2][mo+1]);
                mma_bf16(acc[nb], al[ks], bh[a2][mo], bh[a2][mo+1]);
            }
        }
        __syncthreads();
    }

    int r0 = rb + w*16 + g;
    #pragma unroll
    for (int nb = 0; nb < 8; nb++) {
        int c = cb + 8*nb + 2*q;
        float b0 = bo[c], b1 = bo[c + 1];
        *(float2*)(out + (size_t)r0*D_ + c) =
            make_float2(acc[nb][0] + b0, acc[nb][1] + b1);
        *(float2*)(out + (size_t)(r0 + 8)*D_ + c) =
            make_float2(acc[nb][2] + b0, acc[nb][3] + b1);
    }
}

// ======================= launch ============================================
extern "C" void kernel_launch(void* const* d_in, const int* in_sizes, int n_in,
                              void* d_out, int out_size)
{
    const float* xyz = (const float*)d_in[0];
    const float* Wq  = (const float*)d_in[1];
    const float* Wk  = (const float*)d_in[2];
    const float* Wv  = (const float*)d_in[3];
    const float* Wo  = (const float*)d_in[4];
    const float* bo  = (const float*)d_in[5];
    float* out = (float*)d_out;

    int store_attn = (out_size >= (int)(OUT_ELEMS + ATTN_ELEMS)) ? 1 : 0;
    float* attn = store_attn ? (out + OUT_ELEMS) : out;

    cudaFuncSetAttribute(qkv_kernel, cudaFuncAttributeMaxDynamicSharedMemorySize,
                         QKV_SMEM_FLOATS * 4);
    cudaFuncSetAttribute(attn_mma_kernel, cudaFuncAttributeMaxDynamicSharedMemorySize,
                         ATTN_SMEM_BYTES);
    cudaFuncSetAttribute(proj_mma_kernel, cudaFuncAttributeMaxDynamicSharedMemorySize,
                         PROJ_SMEM_BYTES);

    qkv_kernel<<<(N_*P_)/QKV_RPB, 512, QKV_SMEM_FLOATS*4>>>(xyz, Wq, Wk, Wv, Wo);
    attn_mma_kernel<<<dim3(P_/QT, H_, N_), 128, ATTN_SMEM_BYTES>>>(attn, store_attn);
    proj_mma_kernel<<<dim3((N_*P_)/64, D_/64), 128, PROJ_SMEM_BYTES>>>(bo, out);
}